// round 9
// baseline (speedup 1.0000x reference)
#include <cuda_runtime.h>
#include <cuda_fp16.h>
#include <math.h>
#include <cstdint>

// Problem constants.
#define NN 65536
#define KK 8
#define HH 128
#define TT 4

#define NTF 16
#define GRID_F (NN / NTF + TT)

// fp16 tile rows: 128 halves padded to 136 (272 bytes, bank-stride 4 -> conflict-free).
#define ROWB 272

// ---- fused kernel smem map (bytes) ----
#define S_NODE 0         // 16 ints
#define S_BST  64        // 384 f32 iou bias = 1536
#define S_FI   1600      // 16*128 f32 = 8192
#define S_A    9792      // h fp16 [128 rows][136h] = 34816
#define S_B    44608     // B fp16 [128 k][136h]   = 34816 (forget B, then iou B chunks)
#define S_A2   79424     // hsum fp16 [16][136h]   = 4352
#define S_SMEM 83776

// ---------------- device scratch ----------------
__device__ int g_base[TT + 1];
__device__ int g_cursor[TT];
__device__ int g_sorted[NN];

// ---------------- helpers ----------------
__device__ __forceinline__ uint32_t smem_u32(const void* p) {
    uint32_t a;
    asm("{ .reg .u64 t; cvta.to.shared.u64 t, %1; cvt.u32.u64 %0, t; }" : "=r"(a) : "l"(p));
    return a;
}
__device__ __forceinline__ uint32_t h2u(float x, float y) {
    __half2 h = __floats2half2_rn(x, y);
    return *reinterpret_cast<uint32_t*>(&h);
}
__device__ __forceinline__ void ldsm4(uint32_t* r, uint32_t a) {
    asm volatile("ldmatrix.sync.aligned.m8n8.x4.shared.b16 {%0,%1,%2,%3}, [%4];"
        : "=r"(r[0]), "=r"(r[1]), "=r"(r[2]), "=r"(r[3]) : "r"(a));
}
__device__ __forceinline__ void ldsm4t(uint32_t* r, uint32_t a) {
    asm volatile("ldmatrix.sync.aligned.m8n8.x4.trans.shared.b16 {%0,%1,%2,%3}, [%4];"
        : "=r"(r[0]), "=r"(r[1]), "=r"(r[2]), "=r"(r[3]) : "r"(a));
}
__device__ __forceinline__ void mma16(float* d, const uint32_t* a, uint32_t b0, uint32_t b1) {
    asm volatile("mma.sync.aligned.m16n8k16.row.col.f32.f16.f16.f32 "
        "{%0,%1,%2,%3}, {%4,%5,%6,%7}, {%8,%9}, {%0,%1,%2,%3};"
        : "+f"(d[0]), "+f"(d[1]), "+f"(d[2]), "+f"(d[3])
        : "r"(a[0]), "r"(a[1]), "r"(a[2]), "r"(a[3]), "r"(b0), "r"(b1));
}
__device__ __forceinline__ float sigm(float x) { return 1.f / (1.f + __expf(-x)); }

__device__ __forceinline__ bool find_chunk(int b, int NT, int& t, int& rowstart, int& cnt) {
    int cb = 0;
#pragma unroll
    for (int tt = 0; tt < TT; tt++) {
        int lo = g_base[tt], hi = g_base[tt + 1];
        int ch = (hi - lo + NT - 1) / NT;
        if (b >= cb && b < cb + ch) {
            t = tt;
            rowstart = lo + (b - cb) * NT;
            cnt = min(NT, hi - rowstart);
            return true;
        }
        cb += ch;
    }
    return false;
}

// ---------------- partition: histogram + scan in one CTA ----------------
__global__ __launch_bounds__(1024) void k_part1(const int* __restrict__ type_id) {
    __shared__ int sc[TT];
    int tid = threadIdx.x;
    if (tid < TT) sc[tid] = 0;
    __syncthreads();
    int c0 = 0, c1 = 0, c2 = 0, c3 = 0;
    const int4* p = (const int4*)type_id;
    for (int i = tid; i < NN / 4; i += 1024) {
        int4 v = p[i];
        c0 += (v.x == 0) + (v.y == 0) + (v.z == 0) + (v.w == 0);
        c1 += (v.x == 1) + (v.y == 1) + (v.z == 1) + (v.w == 1);
        c2 += (v.x == 2) + (v.y == 2) + (v.z == 2) + (v.w == 2);
        c3 += (v.x == 3) + (v.y == 3) + (v.z == 3) + (v.w == 3);
    }
#pragma unroll
    for (int d = 16; d; d >>= 1) {
        c0 += __shfl_xor_sync(0xffffffffu, c0, d);
        c1 += __shfl_xor_sync(0xffffffffu, c1, d);
        c2 += __shfl_xor_sync(0xffffffffu, c2, d);
        c3 += __shfl_xor_sync(0xffffffffu, c3, d);
    }
    if ((tid & 31) == 0) {
        atomicAdd(&sc[0], c0); atomicAdd(&sc[1], c1);
        atomicAdd(&sc[2], c2); atomicAdd(&sc[3], c3);
    }
    __syncthreads();
    if (tid == 0) {
        int b = 0;
#pragma unroll
        for (int t = 0; t < TT; t++) { g_base[t] = b; g_cursor[t] = b; b += sc[t]; }
        g_base[TT] = b;
    }
}

__global__ void k_scatter(const int* __restrict__ type_id) {
    __shared__ int w_off[8][TT];
    __shared__ int blk_base[TT];
    int n = blockIdx.x * 256 + threadIdx.x;
    int t = type_id[n];
    int w = threadIdx.x >> 5, lane = threadIdx.x & 31;
    int rank = 0;
#pragma unroll
    for (int tt = 0; tt < TT; tt++) {
        unsigned bm = __ballot_sync(0xffffffffu, t == tt);
        if (lane == 0) w_off[w][tt] = __popc(bm);
        if (t == tt) rank = __popc(bm & ((1u << lane) - 1));
    }
    __syncthreads();
    if (threadIdx.x < TT) {
        int tt = threadIdx.x, s = 0;
#pragma unroll
        for (int ww = 0; ww < 8; ww++) { int v = w_off[ww][tt]; w_off[ww][tt] = s; s += v; }
        blk_base[tt] = atomicAdd(&g_cursor[tt], s);
    }
    __syncthreads();
    g_sorted[blk_base[t] + w_off[w][t] + rank] = n;
}

// ---------------- fused kernel ----------------
// CTA = 16 same-type nodes.
// Phase 1: stage h (fp16, M=128 rows), hsum->A2 (fp16, 16 rows), B_f = U_f[t] as [k][n], fi, bias.
// Phase 2: forget GEMM (M128 N128 K128) + sigmoid*c child-reduce epilogue -> out[:,384:512].
// Phase 3: iou GEMM (M16 N384 K128) in 3 N-chunks from U_iou[t] -> out[:,0:384].
__global__ __launch_bounds__(256, 2) void k_fused(
    const float* __restrict__ h, const float* __restrict__ c,
    const float* __restrict__ f_input,
    const float* __restrict__ U_iou, const float* __restrict__ b_iou,
    const float* __restrict__ U_f, const float* __restrict__ b_f,
    float* __restrict__ out)
{
    extern __shared__ __align__(1024) char smem[];
    const uint32_t sb = smem_u32(smem);
    const int tid = threadIdx.x, wid = tid >> 5, lane = tid & 31;

    int t, rowstart, cnt;
    if (!find_chunk(blockIdx.x, NTF, t, rowstart, cnt)) return;

    int* sh_node = (int*)(smem + S_NODE);
    float* bst = (float*)(smem + S_BST);
    float* fi = (float*)(smem + S_FI);
    if (tid < NTF) sh_node[tid] = g_sorted[rowstart + min(tid, cnt - 1)];
    __syncthreads();

    // ---- phase 1: loaders ----
    // iou bias stage
    if (tid < 128) {
        bst[tid] = b_iou[t * 384 + tid];
        bst[tid + 128] = b_iou[t * 384 + 128 + tid];
        bst[tid + 256] = b_iou[t * 384 + 256 + tid];
    }
    // fi stage: f_input + b_f (16 x 128)
#pragma unroll
    for (int i = 0; i < 8; i++) {
        int idx = tid + 256 * i;
        int n = idx >> 7, col = idx & 127;
        fi[idx] = f_input[(size_t)sh_node[n] * HH + col] + b_f[t * HH + col];
    }
    // A loader + hsum->A2: task (node, j4); thread covers all 8 children.
#pragma unroll
    for (int i = 0; i < 2; i++) {
        int task = tid + 256 * i;
        int j4 = task & 31, n = task >> 5;
        int nd = sh_node[n];
        float4 s = make_float4(0.f, 0.f, 0.f, 0.f);
#pragma unroll
        for (int ch = 0; ch < KK; ch++) {
            float4 v = *(const float4*)&h[((size_t)nd * KK + ch) * HH + j4 * 4];
            s.x += v.x; s.y += v.y; s.z += v.z; s.w += v.w;
            *(uint2*)(smem + S_A + (n * KK + ch) * ROWB + j4 * 8) =
                make_uint2(h2u(v.x, v.y), h2u(v.z, v.w));
        }
        *(uint2*)(smem + S_A2 + n * ROWB + j4 * 8) = make_uint2(h2u(s.x, s.y), h2u(s.z, s.w));
    }
    // B loader (coalesced): B[k][n] from U_f[t][k][n] (n contiguous).
#pragma unroll
    for (int i = 0; i < 16; i++) {
        int task = tid + 256 * i;
        int n4 = task & 31, k = task >> 5;
        float4 v = *(const float4*)&U_f[(size_t)t * HH * HH + (size_t)k * HH + n4 * 4];
        *(uint2*)(smem + S_B + k * ROWB + n4 * 8) = make_uint2(h2u(v.x, v.y), h2u(v.z, v.w));
    }
    __syncthreads();

    // ---- phase 2: forget GEMM ----
    float acc[16][4];
#pragma unroll
    for (int i = 0; i < 16; i++)
#pragma unroll
        for (int j = 0; j < 4; j++) acc[i][j] = 0.f;

    const int m0 = wid * 16;
    const int klocal = (lane & 7) + ((lane >> 3) & 1) * 8;   // trans row within k16
    const int hi = lane >> 4;                                 // 0/1 sub-chunk
    const uint32_t aaddr = sb + S_A + (m0 + (lane & 15)) * ROWB + hi * 16;
    const uint32_t btaddr = sb + S_B + klocal * ROWB + hi * 16;

#pragma unroll
    for (int ks = 0; ks < 8; ks++) {
        uint32_t af[4];
        ldsm4(af, aaddr + ks * 32);
#pragma unroll
        for (int nb = 0; nb < 8; nb++) {
            uint32_t bf[4];
            ldsm4t(bf, btaddr + ks * 16 * ROWB + nb * 32);
            mma16(acc[2 * nb], af, bf[0], bf[1]);
            mma16(acc[2 * nb + 1], af, bf[2], bf[3]);
        }
    }

    // forget epilogue: sigmoid * c, reduce 8 children, store out[:,384:512]
    {
        const int node0 = wid * 2, node1 = node0 + 1;
        const int child = lane >> 2, q = lane & 3;
        const int nd0 = sh_node[node0], nd1 = sh_node[node1];
        const float* c0p = c + ((size_t)nd0 * KK + child) * HH;
        const float* c1p = c + ((size_t)nd1 * KK + child) * HH;
#pragma unroll
        for (int nt = 0; nt < 16; nt++) {
            int col = nt * 8 + 2 * q;
            float2 f0 = *(float2*)&fi[node0 * 128 + col];
            float2 f1 = *(float2*)&fi[node1 * 128 + col];
            float2 cv0 = *(const float2*)(c0p + col);
            float2 cv1 = *(const float2*)(c1p + col);
            float v00 = sigm(acc[nt][0] + f0.x) * cv0.x;
            float v01 = sigm(acc[nt][1] + f0.y) * cv0.y;
            float v10 = sigm(acc[nt][2] + f1.x) * cv1.x;
            float v11 = sigm(acc[nt][3] + f1.y) * cv1.y;
#pragma unroll
            for (int d = 4; d < 32; d <<= 1) {
                v00 += __shfl_xor_sync(0xffffffffu, v00, d);
                v01 += __shfl_xor_sync(0xffffffffu, v01, d);
                v10 += __shfl_xor_sync(0xffffffffu, v10, d);
                v11 += __shfl_xor_sync(0xffffffffu, v11, d);
            }
            if (lane < 4 && node0 < cnt)
                *(float2*)&out[(size_t)nd0 * 512 + 384 + nt * 8 + 2 * lane] = make_float2(v00, v01);
            if (lane >= 4 && lane < 8 && node1 < cnt)
                *(float2*)&out[(size_t)nd1 * 512 + 384 + nt * 8 + 2 * (lane - 4)] = make_float2(v10, v11);
        }
    }

    // ---- phase 3: iou GEMM (M=16, warp w owns n16 columns [w*16, w*16+16)) ----
    const uint32_t a2addr = sb + S_A2 + (lane & 15) * ROWB + hi * 16;
    const uint32_t btaddr2 = sb + S_B + klocal * ROWB + wid * 32 + hi * 16;

    for (int nc = 0; nc < 3; nc++) {
        __syncthreads();   // everyone done reading B (forget mma / previous chunk)
        // B chunk loader: [k][n128] from U_iou[t][k][nc*128 + n]
#pragma unroll
        for (int i = 0; i < 16; i++) {
            int task = tid + 256 * i;
            int n4 = task & 31, k = task >> 5;
            float4 v = *(const float4*)&U_iou[(size_t)t * HH * 384 + (size_t)k * 384 + nc * 128 + n4 * 4];
            *(uint2*)(smem + S_B + k * ROWB + n4 * 8) = make_uint2(h2u(v.x, v.y), h2u(v.z, v.w));
        }
        __syncthreads();

        float a2[2][4];
#pragma unroll
        for (int g = 0; g < 2; g++)
#pragma unroll
            for (int j = 0; j < 4; j++) a2[g][j] = 0.f;

#pragma unroll
        for (int ks = 0; ks < 8; ks++) {
            uint32_t af[4];
            ldsm4(af, a2addr + ks * 32);
            uint32_t bf[4];
            ldsm4t(bf, btaddr2 + ks * 16 * ROWB);
            mma16(a2[0], af, bf[0], bf[1]);
            mma16(a2[1], af, bf[2], bf[3]);
        }

        // iou epilogue: bias + store out[:, nc*128 + wid*16 ...]
        const int r0 = lane >> 2, r1 = r0 + 8;
        const int q = lane & 3;
#pragma unroll
        for (int g = 0; g < 2; g++) {
            int col = wid * 16 + g * 8 + 2 * q;
            float2 b2 = *(float2*)&bst[nc * 128 + col];
            if (r0 < cnt)
                *(float2*)&out[(size_t)sh_node[r0] * 512 + nc * 128 + col] =
                    make_float2(a2[g][0] + b2.x, a2[g][1] + b2.y);
            if (r1 < cnt)
                *(float2*)&out[(size_t)sh_node[r1] * 512 + nc * 128 + col] =
                    make_float2(a2[g][2] + b2.x, a2[g][3] + b2.y);
        }
    }
}

// ---------------- launch ----------------
extern "C" void kernel_launch(void* const* d_in, const int* in_sizes, int n_in,
                              void* d_out, int out_size) {
    const float* h       = (const float*)d_in[0];
    const float* c       = (const float*)d_in[1];
    const float* f_input = (const float*)d_in[2];
    const int*   type_id = (const int*)d_in[3];
    const float* U_iou   = (const float*)d_in[4];
    const float* b_iou   = (const float*)d_in[5];
    const float* U_f     = (const float*)d_in[6];
    const float* b_f     = (const float*)d_in[7];
    float* out = (float*)d_out;

    static int attr_done = 0;
    if (!attr_done) {
        cudaFuncSetAttribute(k_fused, cudaFuncAttributeMaxDynamicSharedMemorySize, S_SMEM);
        attr_done = 1;
    }

    k_part1<<<1, 1024>>>(type_id);
    k_scatter<<<NN / 256, 256>>>(type_id);
    k_fused<<<GRID_F, 256, S_SMEM>>>(h, c, f_input, U_iou, b_iou, U_f, b_f, out);
}

// round 11
// speedup vs baseline: 1.1242x; 1.1242x over previous
#include <cuda_runtime.h>
#include <cuda_fp16.h>
#include <math.h>
#include <cstdint>

// Problem constants.
#define NN 65536
#define KK 8
#define HH 128
#define TT 4

#define NTF 16
#define GRID_F (NN / NTF + TT)
#define NTI 128
#define GRID_I (NN / NTI + TT)

// fp16 tile rows: 128 halves padded to 136 (272 bytes -> 4-bank row rotation, conflict-free).
#define ROWB 272

// ---- k_forget smem map (bytes): 70656 -> 3 CTAs/SM ----
#define F_NODE 0
#define F_BF   64
#define F_A    1024
#define F_B    (F_A + 34816)
#define F_SMEM (F_B + 34816)

// ---- k_iou smem map: 71680 -> 3 CTAs/SM ----
#define I_NODE 0
#define I_BST  512
#define I_A    2048
#define I_B    (I_A + 34816)
#define I_SMEM (I_B + 34816)

// ---------------- device scratch ----------------
__device__ int g_cnt[TT];
__device__ int g_base[TT + 1];
__device__ int g_cursor[TT];
__device__ int g_sorted[NN];
__device__ float g_hsum[NN * HH];

// ---------------- helpers ----------------
__device__ __forceinline__ uint32_t smem_u32(const void* p) {
    uint32_t a;
    asm("{ .reg .u64 t; cvta.to.shared.u64 t, %1; cvt.u32.u64 %0, t; }" : "=r"(a) : "l"(p));
    return a;
}
__device__ __forceinline__ uint32_t h2u(float x, float y) {
    __half2 h = __floats2half2_rn(x, y);
    return *reinterpret_cast<uint32_t*>(&h);
}
__device__ __forceinline__ void ldsm4(uint32_t* r, uint32_t a) {
    asm volatile("ldmatrix.sync.aligned.m8n8.x4.shared.b16 {%0,%1,%2,%3}, [%4];"
        : "=r"(r[0]), "=r"(r[1]), "=r"(r[2]), "=r"(r[3]) : "r"(a));
}
__device__ __forceinline__ void ldsm4t(uint32_t* r, uint32_t a) {
    asm volatile("ldmatrix.sync.aligned.m8n8.x4.trans.shared.b16 {%0,%1,%2,%3}, [%4];"
        : "=r"(r[0]), "=r"(r[1]), "=r"(r[2]), "=r"(r[3]) : "r"(a));
}
__device__ __forceinline__ void mma16(float* d, const uint32_t* a, uint32_t b0, uint32_t b1) {
    asm volatile("mma.sync.aligned.m16n8k16.row.col.f32.f16.f16.f32 "
        "{%0,%1,%2,%3}, {%4,%5,%6,%7}, {%8,%9}, {%0,%1,%2,%3};"
        : "+f"(d[0]), "+f"(d[1]), "+f"(d[2]), "+f"(d[3])
        : "r"(a[0]), "r"(a[1]), "r"(a[2]), "r"(a[3]), "r"(b0), "r"(b1));
}
__device__ __forceinline__ float sigm(float x) { return 1.f / (1.f + __expf(-x)); }

__device__ __forceinline__ bool find_chunk(int b, int NT, int& t, int& rowstart, int& cnt) {
    int cb = 0;
#pragma unroll
    for (int tt = 0; tt < TT; tt++) {
        int lo = g_base[tt], hi = g_base[tt + 1];
        int ch = (hi - lo + NT - 1) / NT;
        if (b >= cb && b < cb + ch) {
            t = tt;
            rowstart = lo + (b - cb) * NT;
            cnt = min(NT, hi - rowstart);
            return true;
        }
        cb += ch;
    }
    return false;
}

// ---------------- partition pipeline ----------------
__global__ void k_zero() {
    if (threadIdx.x < TT) g_cnt[threadIdx.x] = 0;
}
__global__ void k_hist(const int* __restrict__ type_id) {
    __shared__ int sc[TT];
    if (threadIdx.x < TT) sc[threadIdx.x] = 0;
    __syncthreads();
    int i = blockIdx.x * 256 + threadIdx.x;
    int4 v = ((const int4*)type_id)[i];
    atomicAdd(&sc[v.x], 1);
    atomicAdd(&sc[v.y], 1);
    atomicAdd(&sc[v.z], 1);
    atomicAdd(&sc[v.w], 1);
    __syncthreads();
    if (threadIdx.x < TT) atomicAdd(&g_cnt[threadIdx.x], sc[threadIdx.x]);
}
__global__ void k_scan() {
    int b = 0;
#pragma unroll
    for (int t = 0; t < TT; t++) { g_base[t] = b; g_cursor[t] = b; b += g_cnt[t]; }
    g_base[TT] = b;
}
__global__ void k_scatter(const int* __restrict__ type_id) {
    __shared__ int w_off[8][TT];
    __shared__ int blk_base[TT];
    int n = blockIdx.x * 256 + threadIdx.x;
    int t = type_id[n];
    int w = threadIdx.x >> 5, lane = threadIdx.x & 31;
    int rank = 0;
#pragma unroll
    for (int tt = 0; tt < TT; tt++) {
        unsigned bm = __ballot_sync(0xffffffffu, t == tt);
        if (lane == 0) w_off[w][tt] = __popc(bm);
        if (t == tt) rank = __popc(bm & ((1u << lane) - 1));
    }
    __syncthreads();
    if (threadIdx.x < TT) {
        int tt = threadIdx.x, s = 0;
#pragma unroll
        for (int ww = 0; ww < 8; ww++) { int v = w_off[ww][tt]; w_off[ww][tt] = s; s += v; }
        blk_base[tt] = atomicAdd(&g_cursor[tt], s);
    }
    __syncthreads();
    g_sorted[blk_base[t] + w_off[w][t] + rank] = n;
}

// ---------------- forget-gate GEMM (fp16, nb-outer interleaved epilogue) ----------------
// CTA = 16 same-type nodes -> M=128 rows (node*8+child), N=128, K=128.
// Side product g_hsum. Per-n16-chunk: prefetch c, mma, sigmoid*c child-reduce, store.
__global__ __launch_bounds__(256, 3) void k_forget(
    const float* __restrict__ h, const float* __restrict__ c,
    const float* __restrict__ f_input, const float* __restrict__ U_f,
    const float* __restrict__ b_f, float* __restrict__ out)
{
    extern __shared__ __align__(1024) char smem[];
    const uint32_t sb = smem_u32(smem);
    const int tid = threadIdx.x, wid = tid >> 5, lane = tid & 31;

    int t, rowstart, cnt;
    if (!find_chunk(blockIdx.x, NTF, t, rowstart, cnt)) return;

    int* sh_node = (int*)(smem + F_NODE);
    float* sbf = (float*)(smem + F_BF);
    if (tid < NTF) sh_node[tid] = g_sorted[rowstart + min(tid, cnt - 1)];
    if (tid >= 128) sbf[tid - 128] = b_f[t * HH + (tid - 128)];
    __syncthreads();

    // A loader + f32 hsum: task (node, j4); thread covers all 8 children.
#pragma unroll
    for (int i = 0; i < 2; i++) {
        int task = tid + 256 * i;
        int j4 = task & 31, n = task >> 5;
        int nd = sh_node[n];
        float4 s = make_float4(0.f, 0.f, 0.f, 0.f);
#pragma unroll
        for (int ch = 0; ch < KK; ch++) {
            float4 v = *(const float4*)&h[((size_t)nd * KK + ch) * HH + j4 * 4];
            s.x += v.x; s.y += v.y; s.z += v.z; s.w += v.w;
            *(uint2*)(smem + F_A + (n * KK + ch) * ROWB + j4 * 8) =
                make_uint2(h2u(v.x, v.y), h2u(v.z, v.w));
        }
        *(float4*)&g_hsum[(size_t)nd * HH + j4 * 4] = s;
    }
    // B loader (coalesced): B[k][n] from U_f[t][k][n].
#pragma unroll
    for (int i = 0; i < 16; i++) {
        int task = tid + 256 * i;
        int n4 = task & 31, k = task >> 5;
        float4 v = *(const float4*)&U_f[(size_t)t * HH * HH + (size_t)k * HH + n4 * 4];
        *(uint2*)(smem + F_B + k * ROWB + n4 * 8) = make_uint2(h2u(v.x, v.y), h2u(v.z, v.w));
    }
    __syncthreads();

    // Preload all A fragments (8 k-steps x 4 regs).
    const int m0 = wid * 16;
    const uint32_t aaddr = sb + F_A + (m0 + (lane & 15)) * ROWB + ((lane >> 4) << 4);
    uint32_t af[8][4];
#pragma unroll
    for (int ks = 0; ks < 8; ks++) ldsm4(af[ks], aaddr + ks * 32);

    const int klocal = (lane & 7) + ((lane >> 3) & 1) * 8;
    const uint32_t btaddr = sb + F_B + klocal * ROWB + (lane >> 4) * 16;

    const int node0 = wid * 2, node1 = node0 + 1;
    const int child = lane >> 2, q = lane & 3;
    const int nd0 = sh_node[node0], nd1 = sh_node[node1];
    const float* c0p = c + ((size_t)nd0 * KK + child) * HH;
    const float* c1p = c + ((size_t)nd1 * KK + child) * HH;
    const float* f0p = f_input + (size_t)nd0 * HH;
    const float* f1p = f_input + (size_t)nd1 * HH;

#pragma unroll 1
    for (int nb = 0; nb < 8; nb++) {
        const int colbase = nb * 16 + 2 * q;
        // prefetch c for this chunk (overlaps the mma below)
        float2 cv00 = *(const float2*)(c0p + colbase);
        float2 cv01 = *(const float2*)(c0p + colbase + 8);
        float2 cv10 = *(const float2*)(c1p + colbase);
        float2 cv11 = *(const float2*)(c1p + colbase + 8);

        float acc0[4] = {0.f, 0.f, 0.f, 0.f};
        float acc1[4] = {0.f, 0.f, 0.f, 0.f};
#pragma unroll
        for (int ks = 0; ks < 8; ks++) {
            uint32_t bf4[4];
            ldsm4t(bf4, btaddr + ks * 16 * ROWB + nb * 32);
            mma16(acc0, af[ks], bf4[0], bf4[1]);
            mma16(acc1, af[ks], bf4[2], bf4[3]);
        }

        // epilogue for cols [nb*16, nb*16+16)
        float2 f00 = *(const float2*)(f0p + colbase);
        float2 f01 = *(const float2*)(f0p + colbase + 8);
        float2 f10 = *(const float2*)(f1p + colbase);
        float2 f11 = *(const float2*)(f1p + colbase + 8);
        float2 bf0 = *(float2*)&sbf[colbase];
        float2 bf1 = *(float2*)&sbf[colbase + 8];

        float v00 = sigm(acc0[0] + f00.x + bf0.x) * cv00.x;
        float v01 = sigm(acc0[1] + f00.y + bf0.y) * cv00.y;
        float v10 = sigm(acc0[2] + f10.x + bf0.x) * cv10.x;
        float v11 = sigm(acc0[3] + f10.y + bf0.y) * cv10.y;
        float w00 = sigm(acc1[0] + f01.x + bf1.x) * cv01.x;
        float w01 = sigm(acc1[1] + f01.y + bf1.y) * cv01.y;
        float w10 = sigm(acc1[2] + f11.x + bf1.x) * cv11.x;
        float w11 = sigm(acc1[3] + f11.y + bf1.y) * cv11.y;
#pragma unroll
        for (int d = 4; d < 32; d <<= 1) {
            v00 += __shfl_xor_sync(0xffffffffu, v00, d);
            v01 += __shfl_xor_sync(0xffffffffu, v01, d);
            v10 += __shfl_xor_sync(0xffffffffu, v10, d);
            v11 += __shfl_xor_sync(0xffffffffu, v11, d);
            w00 += __shfl_xor_sync(0xffffffffu, w00, d);
            w01 += __shfl_xor_sync(0xffffffffu, w01, d);
            w10 += __shfl_xor_sync(0xffffffffu, w10, d);
            w11 += __shfl_xor_sync(0xffffffffu, w11, d);
        }
        if (lane < 4 && node0 < cnt) {
            *(float2*)&out[(size_t)nd0 * 512 + 384 + nb * 16 + 2 * lane] = make_float2(v00, v01);
            *(float2*)&out[(size_t)nd0 * 512 + 384 + nb * 16 + 8 + 2 * lane] = make_float2(w00, w01);
        }
        if (lane >= 4 && lane < 8 && node1 < cnt) {
            *(float2*)&out[(size_t)nd1 * 512 + 384 + nb * 16 + 2 * (lane - 4)] = make_float2(v10, v11);
            *(float2*)&out[(size_t)nd1 * 512 + 384 + nb * 16 + 8 + 2 * (lane - 4)] = make_float2(w10, w11);
        }
    }
}

// ---------------- iou GEMM (fp16, nb-outer) ----------------
// CTA = 128 same-type nodes. D = hsum @ U_iou[t] + b_iou. 3 N-chunks of 128.
__global__ __launch_bounds__(256, 3) void k_iou(
    const float* __restrict__ U_iou, const float* __restrict__ b_iou,
    float* __restrict__ out)
{
    extern __shared__ __align__(1024) char smem[];
    const uint32_t sb = smem_u32(smem);
    const int tid = threadIdx.x, wid = tid >> 5, lane = tid & 31;

    int t, rowstart, cnt;
    if (!find_chunk(blockIdx.x, NTI, t, rowstart, cnt)) return;

    int* sh_node = (int*)(smem + I_NODE);
    float* bst = (float*)(smem + I_BST);
    if (tid < 128) {
        sh_node[tid] = g_sorted[rowstart + min(tid, cnt - 1)];
        bst[tid] = b_iou[t * 384 + tid];
        bst[tid + 128] = b_iou[t * 384 + 128 + tid];
        bst[tid + 256] = b_iou[t * 384 + 256 + tid];
    }
    __syncthreads();

    // A loader: [128 m][128 k] fp16 from g_hsum.
#pragma unroll
    for (int i = 0; i < 16; i++) {
        int task = tid + 256 * i;
        int m = task >> 5, j4 = task & 31;
        float4 v = *(const float4*)&g_hsum[(size_t)sh_node[m] * HH + j4 * 4];
        *(uint2*)(smem + I_A + m * ROWB + j4 * 8) = make_uint2(h2u(v.x, v.y), h2u(v.z, v.w));
    }
    __syncthreads();

    // Preload A fragments.
    const int m0 = wid * 16;
    const uint32_t aaddr = sb + I_A + (m0 + (lane & 15)) * ROWB + ((lane >> 4) << 4);
    uint32_t af[8][4];
#pragma unroll
    for (int ks = 0; ks < 8; ks++) ldsm4(af[ks], aaddr + ks * 32);

    const int klocal = (lane & 7) + ((lane >> 3) & 1) * 8;
    const uint32_t btaddr = sb + I_B + klocal * ROWB + (lane >> 4) * 16;
    const int r0 = m0 + (lane >> 2), r1 = r0 + 8;
    const int q = lane & 3;
    const int nr0 = sh_node[r0], nr1 = sh_node[r1];

    for (int nc = 0; nc < 3; nc++) {
        if (nc > 0) __syncthreads();   // previous chunk's mma done before B overwrite
        // B chunk loader (coalesced): B[k][n128] from U_iou[t][k][nc*128+n].
#pragma unroll
        for (int i = 0; i < 16; i++) {
            int task = tid + 256 * i;
            int n4 = task & 31, k = task >> 5;
            float4 v = *(const float4*)&U_iou[(size_t)t * HH * 384 + (size_t)k * 384 + nc * 128 + n4 * 4];
            *(uint2*)(smem + I_B + k * ROWB + n4 * 8) = make_uint2(h2u(v.x, v.y), h2u(v.z, v.w));
        }
        __syncthreads();

#pragma unroll 1
        for (int nb = 0; nb < 8; nb++) {
            float acc0[4] = {0.f, 0.f, 0.f, 0.f};
            float acc1[4] = {0.f, 0.f, 0.f, 0.f};
#pragma unroll
            for (int ks = 0; ks < 8; ks++) {
                uint32_t bf4[4];
                ldsm4t(bf4, btaddr + ks * 16 * ROWB + nb * 32);
                mma16(acc0, af[ks], bf4[0], bf4[1]);
                mma16(acc1, af[ks], bf4[2], bf4[3]);
            }
            const int colbase = nb * 16 + 2 * q;
            float2 b20 = *(float2*)&bst[nc * 128 + colbase];
            float2 b21 = *(float2*)&bst[nc * 128 + colbase + 8];
            if (r0 < cnt) {
                *(float2*)&out[(size_t)nr0 * 512 + nc * 128 + colbase] =
                    make_float2(acc0[0] + b20.x, acc0[1] + b20.y);
                *(float2*)&out[(size_t)nr0 * 512 + nc * 128 + colbase + 8] =
                    make_float2(acc1[0] + b21.x, acc1[1] + b21.y);
            }
            if (r1 < cnt) {
                *(float2*)&out[(size_t)nr1 * 512 + nc * 128 + colbase] =
                    make_float2(acc0[2] + b20.x, acc0[3] + b20.y);
                *(float2*)&out[(size_t)nr1 * 512 + nc * 128 + colbase + 8] =
                    make_float2(acc1[2] + b21.x, acc1[3] + b21.y);
            }
        }
    }
}

// ---------------- launch ----------------
extern "C" void kernel_launch(void* const* d_in, const int* in_sizes, int n_in,
                              void* d_out, int out_size) {
    const float* h       = (const float*)d_in[0];
    const float* c       = (const float*)d_in[1];
    const float* f_input = (const float*)d_in[2];
    const int*   type_id = (const int*)d_in[3];
    const float* U_iou   = (const float*)d_in[4];
    const float* b_iou   = (const float*)d_in[5];
    const float* U_f     = (const float*)d_in[6];
    const float* b_f     = (const float*)d_in[7];
    float* out = (float*)d_out;

    static int attr_done = 0;
    if (!attr_done) {
        cudaFuncSetAttribute(k_forget, cudaFuncAttributeMaxDynamicSharedMemorySize, F_SMEM);
        cudaFuncSetAttribute(k_iou, cudaFuncAttributeMaxDynamicSharedMemorySize, I_SMEM);
        attr_done = 1;
    }

    k_zero<<<1, 32>>>();
    k_hist<<<NN / 1024, 256>>>(type_id);
    k_scan<<<1, 1>>>();
    k_scatter<<<NN / 256, 256>>>(type_id);
    k_forget<<<GRID_F, 256, F_SMEM>>>(h, c, f_input, U_f, b_f, out);
    k_iou<<<GRID_I, 256, I_SMEM>>>(U_iou, b_iou, out);
}

// round 12
// speedup vs baseline: 1.2698x; 1.1295x over previous
#include <cuda_runtime.h>
#include <cuda_fp16.h>
#include <math.h>
#include <cstdint>

// Problem constants.
#define NN 65536
#define KK 8
#define HH 128
#define TT 4

#define NTF 16
#define GRID_F (NN / NTF + TT)
#define NTI 64
#define GRID_I (NN / NTI + TT)

// fp16 tile rows: 128 halves padded to 136 (272 bytes -> 4-bank row rotation, conflict-free).
#define ROWB 272

// ---- k_forget smem map (bytes): ~70.6KB -> 3 CTAs/SM ----
#define F_NODE 0
#define F_BF   64
#define F_A    1024
#define F_B    (F_A + 34816)
#define F_SMEM (F_B + 34816)

// ---- k_iou smem map: ~54KB ----
#define I_NODE 0
#define I_BST  512
#define I_A    2048
#define I_B    (I_A + 17408)
#define I_SMEM (I_B + 34816)

// ---------------- device scratch ----------------
__device__ int g_cnt[TT];
__device__ int g_base[TT + 1];
__device__ int g_cursor[TT];
__device__ int g_sorted[NN];
__device__ float g_hsum[NN * HH];

// ---------------- helpers ----------------
__device__ __forceinline__ uint32_t smem_u32(const void* p) {
    uint32_t a;
    asm("{ .reg .u64 t; cvta.to.shared.u64 t, %1; cvt.u32.u64 %0, t; }" : "=r"(a) : "l"(p));
    return a;
}
__device__ __forceinline__ uint32_t h2u(float x, float y) {
    __half2 h = __floats2half2_rn(x, y);
    return *reinterpret_cast<uint32_t*>(&h);
}
__device__ __forceinline__ void pf_l2(const void* p) {
    asm volatile("prefetch.global.L2 [%0];" :: "l"(p));
}
__device__ __forceinline__ void ldsm4(uint32_t* r, uint32_t a) {
    asm volatile("ldmatrix.sync.aligned.m8n8.x4.shared.b16 {%0,%1,%2,%3}, [%4];"
        : "=r"(r[0]), "=r"(r[1]), "=r"(r[2]), "=r"(r[3]) : "r"(a));
}
__device__ __forceinline__ void ldsm4t(uint32_t* r, uint32_t a) {
    asm volatile("ldmatrix.sync.aligned.m8n8.x4.trans.shared.b16 {%0,%1,%2,%3}, [%4];"
        : "=r"(r[0]), "=r"(r[1]), "=r"(r[2]), "=r"(r[3]) : "r"(a));
}
__device__ __forceinline__ void mma16(float* d, const uint32_t* a, uint32_t b0, uint32_t b1) {
    asm volatile("mma.sync.aligned.m16n8k16.row.col.f32.f16.f16.f32 "
        "{%0,%1,%2,%3}, {%4,%5,%6,%7}, {%8,%9}, {%0,%1,%2,%3};"
        : "+f"(d[0]), "+f"(d[1]), "+f"(d[2]), "+f"(d[3])
        : "r"(a[0]), "r"(a[1]), "r"(a[2]), "r"(a[3]), "r"(b0), "r"(b1));
}
__device__ __forceinline__ float sigm(float x) { return 1.f / (1.f + __expf(-x)); }

__device__ __forceinline__ bool find_chunk(int b, int NT, int& t, int& rowstart, int& cnt) {
    int cb = 0;
#pragma unroll
    for (int tt = 0; tt < TT; tt++) {
        int lo = g_base[tt], hi = g_base[tt + 1];
        int ch = (hi - lo + NT - 1) / NT;
        if (b >= cb && b < cb + ch) {
            t = tt;
            rowstart = lo + (b - cb) * NT;
            cnt = min(NT, hi - rowstart);
            return true;
        }
        cb += ch;
    }
    return false;
}

// ---------------- partition pipeline ----------------
__global__ void k_zero() {
    if (threadIdx.x < TT) g_cnt[threadIdx.x] = 0;
}
__global__ void k_hist(const int* __restrict__ type_id) {
    __shared__ int sc[TT];
    if (threadIdx.x < TT) sc[threadIdx.x] = 0;
    __syncthreads();
    int i = blockIdx.x * 256 + threadIdx.x;
    int4 v = ((const int4*)type_id)[i];
    atomicAdd(&sc[v.x], 1);
    atomicAdd(&sc[v.y], 1);
    atomicAdd(&sc[v.z], 1);
    atomicAdd(&sc[v.w], 1);
    __syncthreads();
    if (threadIdx.x < TT) atomicAdd(&g_cnt[threadIdx.x], sc[threadIdx.x]);
}
__global__ void k_scan() {
    int b = 0;
#pragma unroll
    for (int t = 0; t < TT; t++) { g_base[t] = b; g_cursor[t] = b; b += g_cnt[t]; }
    g_base[TT] = b;
}
__global__ void k_scatter(const int* __restrict__ type_id) {
    __shared__ int w_off[8][TT];
    __shared__ int blk_base[TT];
    int n = blockIdx.x * 256 + threadIdx.x;
    int t = type_id[n];
    int w = threadIdx.x >> 5, lane = threadIdx.x & 31;
    int rank = 0;
#pragma unroll
    for (int tt = 0; tt < TT; tt++) {
        unsigned bm = __ballot_sync(0xffffffffu, t == tt);
        if (lane == 0) w_off[w][tt] = __popc(bm);
        if (t == tt) rank = __popc(bm & ((1u << lane) - 1));
    }
    __syncthreads();
    if (threadIdx.x < TT) {
        int tt = threadIdx.x, s = 0;
#pragma unroll
        for (int ww = 0; ww < 8; ww++) { int v = w_off[ww][tt]; w_off[ww][tt] = s; s += v; }
        blk_base[tt] = atomicAdd(&g_cursor[tt], s);
    }
    __syncthreads();
    g_sorted[blk_base[t] + w_off[w][t] + rank] = n;
}

// ---------------- forget-gate GEMM (fp16, nb-outer, L2-prefetched epilogue) ----------------
__global__ __launch_bounds__(256, 3) void k_forget(
    const float* __restrict__ h, const float* __restrict__ c,
    const float* __restrict__ f_input, const float* __restrict__ U_f,
    const float* __restrict__ b_f, float* __restrict__ out)
{
    extern __shared__ __align__(1024) char smem[];
    const uint32_t sb = smem_u32(smem);
    const int tid = threadIdx.x, wid = tid >> 5, lane = tid & 31;

    int t, rowstart, cnt;
    if (!find_chunk(blockIdx.x, NTF, t, rowstart, cnt)) return;

    int* sh_node = (int*)(smem + F_NODE);
    float* sbf = (float*)(smem + F_BF);
    if (tid < NTF) sh_node[tid] = g_sorted[rowstart + min(tid, cnt - 1)];
    if (tid >= 128) sbf[tid - 128] = b_f[t * HH + (tid - 128)];
    __syncthreads();

    const int node0 = wid * 2, node1 = node0 + 1;
    const int nd0 = sh_node[node0], nd1 = sh_node[node1];

    // L2 prefetch for this warp's epilogue streams (c: 4KB/node, f: 512B/node).
    {
        const float* cA = c + (size_t)nd0 * KK * HH;
        const float* cB = c + (size_t)nd1 * KK * HH;
        pf_l2(cA + lane * 32);
        pf_l2(cB + lane * 32);
        if (lane < 4) {
            pf_l2(f_input + (size_t)nd0 * HH + lane * 32);
            pf_l2(f_input + (size_t)nd1 * HH + lane * 32);
        }
    }

    // A loader + f32 hsum: task (node, j4); thread covers all 8 children.
#pragma unroll
    for (int i = 0; i < 2; i++) {
        int task = tid + 256 * i;
        int j4 = task & 31, n = task >> 5;
        int nd = sh_node[n];
        float4 s = make_float4(0.f, 0.f, 0.f, 0.f);
#pragma unroll
        for (int ch = 0; ch < KK; ch++) {
            float4 v = *(const float4*)&h[((size_t)nd * KK + ch) * HH + j4 * 4];
            s.x += v.x; s.y += v.y; s.z += v.z; s.w += v.w;
            *(uint2*)(smem + F_A + (n * KK + ch) * ROWB + j4 * 8) =
                make_uint2(h2u(v.x, v.y), h2u(v.z, v.w));
        }
        *(float4*)&g_hsum[(size_t)nd * HH + j4 * 4] = s;
    }
    // B loader (coalesced): B[k][n] from U_f[t][k][n].
#pragma unroll
    for (int i = 0; i < 16; i++) {
        int task = tid + 256 * i;
        int n4 = task & 31, k = task >> 5;
        float4 v = *(const float4*)&U_f[(size_t)t * HH * HH + (size_t)k * HH + n4 * 4];
        *(uint2*)(smem + F_B + k * ROWB + n4 * 8) = make_uint2(h2u(v.x, v.y), h2u(v.z, v.w));
    }
    __syncthreads();

    // Preload all A fragments.
    const int m0 = wid * 16;
    const uint32_t aaddr = sb + F_A + (m0 + (lane & 15)) * ROWB + ((lane >> 4) << 4);
    uint32_t af[8][4];
#pragma unroll
    for (int ks = 0; ks < 8; ks++) ldsm4(af[ks], aaddr + ks * 32);

    const int klocal = (lane & 7) + ((lane >> 3) & 1) * 8;
    const uint32_t btaddr = sb + F_B + klocal * ROWB + (lane >> 4) * 16;

    const int child = lane >> 2, q = lane & 3;
    const float* c0p = c + ((size_t)nd0 * KK + child) * HH;
    const float* c1p = c + ((size_t)nd1 * KK + child) * HH;
    const float* f0p = f_input + (size_t)nd0 * HH;
    const float* f1p = f_input + (size_t)nd1 * HH;

#pragma unroll 1
    for (int nb = 0; nb < 8; nb++) {
        const int colbase = nb * 16 + 2 * q;
        // issue epilogue loads first (L2-resident via prefetch; covered by mma below)
        float2 cv00 = *(const float2*)(c0p + colbase);
        float2 cv01 = *(const float2*)(c0p + colbase + 8);
        float2 cv10 = *(const float2*)(c1p + colbase);
        float2 cv11 = *(const float2*)(c1p + colbase + 8);
        float2 f00 = *(const float2*)(f0p + colbase);
        float2 f01 = *(const float2*)(f0p + colbase + 8);
        float2 f10 = *(const float2*)(f1p + colbase);
        float2 f11 = *(const float2*)(f1p + colbase + 8);

        float acc0[4] = {0.f, 0.f, 0.f, 0.f};
        float acc1[4] = {0.f, 0.f, 0.f, 0.f};
#pragma unroll
        for (int ks = 0; ks < 8; ks++) {
            uint32_t bf4[4];
            ldsm4t(bf4, btaddr + ks * 16 * ROWB + nb * 32);
            mma16(acc0, af[ks], bf4[0], bf4[1]);
            mma16(acc1, af[ks], bf4[2], bf4[3]);
        }

        float2 bf0 = *(float2*)&sbf[colbase];
        float2 bf1 = *(float2*)&sbf[colbase + 8];

        float v00 = sigm(acc0[0] + f00.x + bf0.x) * cv00.x;
        float v01 = sigm(acc0[1] + f00.y + bf0.y) * cv00.y;
        float v10 = sigm(acc0[2] + f10.x + bf0.x) * cv10.x;
        float v11 = sigm(acc0[3] + f10.y + bf0.y) * cv10.y;
        float w00 = sigm(acc1[0] + f01.x + bf1.x) * cv01.x;
        float w01 = sigm(acc1[1] + f01.y + bf1.y) * cv01.y;
        float w10 = sigm(acc1[2] + f11.x + bf1.x) * cv11.x;
        float w11 = sigm(acc1[3] + f11.y + bf1.y) * cv11.y;
#pragma unroll
        for (int d = 4; d < 32; d <<= 1) {
            v00 += __shfl_xor_sync(0xffffffffu, v00, d);
            v01 += __shfl_xor_sync(0xffffffffu, v01, d);
            v10 += __shfl_xor_sync(0xffffffffu, v10, d);
            v11 += __shfl_xor_sync(0xffffffffu, v11, d);
            w00 += __shfl_xor_sync(0xffffffffu, w00, d);
            w01 += __shfl_xor_sync(0xffffffffu, w01, d);
            w10 += __shfl_xor_sync(0xffffffffu, w10, d);
            w11 += __shfl_xor_sync(0xffffffffu, w11, d);
        }
        if (lane < 4 && node0 < cnt) {
            *(float2*)&out[(size_t)nd0 * 512 + 384 + nb * 16 + 2 * lane] = make_float2(v00, v01);
            *(float2*)&out[(size_t)nd0 * 512 + 384 + nb * 16 + 8 + 2 * lane] = make_float2(w00, w01);
        }
        if (lane >= 4 && lane < 8 && node1 < cnt) {
            *(float2*)&out[(size_t)nd1 * 512 + 384 + nb * 16 + 2 * (lane - 4)] = make_float2(v10, v11);
            *(float2*)&out[(size_t)nd1 * 512 + 384 + nb * 16 + 8 + 2 * (lane - 4)] = make_float2(w10, w11);
        }
    }
}

// ---------------- iou GEMM (fp16, NTI=64 for tail balance) ----------------
// CTA = 64 same-type nodes; warp (m-tile = wid>>1, n-half = wid&1).
__global__ __launch_bounds__(256, 3) void k_iou(
    const float* __restrict__ U_iou, const float* __restrict__ b_iou,
    float* __restrict__ out)
{
    extern __shared__ __align__(1024) char smem[];
    const uint32_t sb = smem_u32(smem);
    const int tid = threadIdx.x, wid = tid >> 5, lane = tid & 31;

    int t, rowstart, cnt;
    if (!find_chunk(blockIdx.x, NTI, t, rowstart, cnt)) return;

    int* sh_node = (int*)(smem + I_NODE);
    float* bst = (float*)(smem + I_BST);
    if (tid < 64) sh_node[tid] = g_sorted[rowstart + min(tid, cnt - 1)];
    if (tid >= 128) {
        int i = tid - 128;
        bst[i] = b_iou[t * 384 + i];
        if (i < 128) { }   // (covered below)
    }
    if (tid >= 64 && tid < 128) {
        int i = tid - 64;
        bst[128 + i] = b_iou[t * 384 + 128 + i];
        bst[256 + i] = b_iou[t * 384 + 256 + i];
    }
    if (tid >= 192) {
        int i = tid - 192;
        bst[128 + 64 + i] = b_iou[t * 384 + 128 + 64 + i];
        bst[256 + 64 + i] = b_iou[t * 384 + 256 + 64 + i];
    }
    __syncthreads();

    // A loader: [64 m][128 k] fp16 from g_hsum.
#pragma unroll
    for (int i = 0; i < 8; i++) {
        int task = tid + 256 * i;
        int m = task >> 5, j4 = task & 31;
        float4 v = *(const float4*)&g_hsum[(size_t)sh_node[m] * HH + j4 * 4];
        *(uint2*)(smem + I_A + m * ROWB + j4 * 8) = make_uint2(h2u(v.x, v.y), h2u(v.z, v.w));
    }
    __syncthreads();

    // Preload A fragments.
    const int m0 = (wid >> 1) * 16;
    const int nh = wid & 1;                 // n-half: cols [nh*64, nh*64+64)
    const uint32_t aaddr = sb + I_A + (m0 + (lane & 15)) * ROWB + ((lane >> 4) << 4);
    uint32_t af[8][4];
#pragma unroll
    for (int ks = 0; ks < 8; ks++) ldsm4(af[ks], aaddr + ks * 32);

    const int klocal = (lane & 7) + ((lane >> 3) & 1) * 8;
    const uint32_t btaddr = sb + I_B + klocal * ROWB + (lane >> 4) * 16 + nh * 128;
    const int r0 = m0 + (lane >> 2), r1 = r0 + 8;
    const int q = lane & 3;
    const int nr0 = sh_node[r0], nr1 = sh_node[r1];

    for (int nc = 0; nc < 3; nc++) {
        if (nc > 0) __syncthreads();
        // B chunk loader (coalesced): B[k][n128] from U_iou[t][k][nc*128+n].
#pragma unroll
        for (int i = 0; i < 16; i++) {
            int task = tid + 256 * i;
            int n4 = task & 31, k = task >> 5;
            float4 v = *(const float4*)&U_iou[(size_t)t * HH * 384 + (size_t)k * 384 + nc * 128 + n4 * 4];
            *(uint2*)(smem + I_B + k * ROWB + n4 * 8) = make_uint2(h2u(v.x, v.y), h2u(v.z, v.w));
        }
        __syncthreads();

#pragma unroll 1
        for (int nb = 0; nb < 4; nb++) {
            float acc0[4] = {0.f, 0.f, 0.f, 0.f};
            float acc1[4] = {0.f, 0.f, 0.f, 0.f};
#pragma unroll
            for (int ks = 0; ks < 8; ks++) {
                uint32_t bf4[4];
                ldsm4t(bf4, btaddr + ks * 16 * ROWB + nb * 32);
                mma16(acc0, af[ks], bf4[0], bf4[1]);
                mma16(acc1, af[ks], bf4[2], bf4[3]);
            }
            const int colbase = nh * 64 + nb * 16 + 2 * q;
            float2 b20 = *(float2*)&bst[nc * 128 + colbase];
            float2 b21 = *(float2*)&bst[nc * 128 + colbase + 8];
            if (r0 < cnt) {
                *(float2*)&out[(size_t)nr0 * 512 + nc * 128 + colbase] =
                    make_float2(acc0[0] + b20.x, acc0[1] + b20.y);
                *(float2*)&out[(size_t)nr0 * 512 + nc * 128 + colbase + 8] =
                    make_float2(acc1[0] + b21.x, acc1[1] + b21.y);
            }
            if (r1 < cnt) {
                *(float2*)&out[(size_t)nr1 * 512 + nc * 128 + colbase] =
                    make_float2(acc0[2] + b20.x, acc0[3] + b20.y);
                *(float2*)&out[(size_t)nr1 * 512 + nc * 128 + colbase + 8] =
                    make_float2(acc1[2] + b21.x, acc1[3] + b21.y);
            }
        }
    }
}

// ---------------- launch ----------------
extern "C" void kernel_launch(void* const* d_in, const int* in_sizes, int n_in,
                              void* d_out, int out_size) {
    const float* h       = (const float*)d_in[0];
    const float* c       = (const float*)d_in[1];
    const float* f_input = (const float*)d_in[2];
    const int*   type_id = (const int*)d_in[3];
    const float* U_iou   = (const float*)d_in[4];
    const float* b_iou   = (const float*)d_in[5];
    const float* U_f     = (const float*)d_in[6];
    const float* b_f     = (const float*)d_in[7];
    float* out = (float*)d_out;

    static int attr_done = 0;
    if (!attr_done) {
        cudaFuncSetAttribute(k_forget, cudaFuncAttributeMaxDynamicSharedMemorySize, F_SMEM);
        cudaFuncSetAttribute(k_iou, cudaFuncAttributeMaxDynamicSharedMemorySize, I_SMEM);
        attr_done = 1;
    }

    k_zero<<<1, 32>>>();
    k_hist<<<NN / 1024, 256>>>(type_id);
    k_scan<<<1, 1>>>();
    k_scatter<<<NN / 256, 256>>>(type_id);
    k_forget<<<GRID_F, 256, F_SMEM>>>(h, c, f_input, U_f, b_f, out);
    k_iou<<<GRID_I, 256, I_SMEM>>>(U_iou, b_iou, out);
}

// round 13
// speedup vs baseline: 1.3102x; 1.0319x over previous
#include <cuda_runtime.h>
#include <cuda_fp16.h>
#include <math.h>
#include <cstdint>

// Problem constants.
#define NN 65536
#define KK 8
#define HH 128
#define TT 4

#define NTF 16
#define GRID_F (NN / NTF + TT)      // 4100 forget-role blocks
#define NTI 64
#define GRID_I (NN / NTI + TT)      // 1028 iou-role blocks

// fp16 tile rows: 128 halves padded to 136 (272 bytes -> conflict-free).
#define ROWB 272

// ---- forget-role smem map (bytes): ~70.6KB -> 3 CTAs/SM ----
#define F_NODE 0
#define F_BF   64
#define F_A    1024
#define F_B    (F_A + 34816)
#define F_SMEM (F_B + 34816)

// ---- iou-role smem map (within same dynamic smem) ----
#define I_NODE 0
#define I_BST  512
#define I_A    2048
#define I_B    (I_A + 17408)

// ---------------- device scratch ----------------
__device__ int g_cnt[TT];
__device__ int g_base[TT + 1];
__device__ int g_cursor[TT];
__device__ int g_sorted[NN];
__device__ float g_hsum[NN * HH];
__device__ int g_flag[GRID_F];

// ---------------- helpers ----------------
__device__ __forceinline__ uint32_t smem_u32(const void* p) {
    uint32_t a;
    asm("{ .reg .u64 t; cvta.to.shared.u64 t, %1; cvt.u32.u64 %0, t; }" : "=r"(a) : "l"(p));
    return a;
}
__device__ __forceinline__ uint32_t h2u(float x, float y) {
    __half2 h = __floats2half2_rn(x, y);
    return *reinterpret_cast<uint32_t*>(&h);
}
__device__ __forceinline__ void pf_l2(const void* p) {
    asm volatile("prefetch.global.L2 [%0];" :: "l"(p));
}
__device__ __forceinline__ int ld_acq(const int* p) {
    int v;
    asm volatile("ld.acquire.gpu.global.b32 %0, [%1];" : "=r"(v) : "l"(p));
    return v;
}
__device__ __forceinline__ void st_rel(int* p, int v) {
    asm volatile("st.release.gpu.global.b32 [%0], %1;" :: "l"(p), "r"(v));
}
__device__ __forceinline__ void ldsm4(uint32_t* r, uint32_t a) {
    asm volatile("ldmatrix.sync.aligned.m8n8.x4.shared.b16 {%0,%1,%2,%3}, [%4];"
        : "=r"(r[0]), "=r"(r[1]), "=r"(r[2]), "=r"(r[3]) : "r"(a));
}
__device__ __forceinline__ void ldsm4t(uint32_t* r, uint32_t a) {
    asm volatile("ldmatrix.sync.aligned.m8n8.x4.trans.shared.b16 {%0,%1,%2,%3}, [%4];"
        : "=r"(r[0]), "=r"(r[1]), "=r"(r[2]), "=r"(r[3]) : "r"(a));
}
__device__ __forceinline__ void mma16(float* d, const uint32_t* a, uint32_t b0, uint32_t b1) {
    asm volatile("mma.sync.aligned.m16n8k16.row.col.f32.f16.f16.f32 "
        "{%0,%1,%2,%3}, {%4,%5,%6,%7}, {%8,%9}, {%0,%1,%2,%3};"
        : "+f"(d[0]), "+f"(d[1]), "+f"(d[2]), "+f"(d[3])
        : "r"(a[0]), "r"(a[1]), "r"(a[2]), "r"(a[3]), "r"(b0), "r"(b1));
}
__device__ __forceinline__ float sigm(float x) { return 1.f / (1.f + __expf(-x)); }

__device__ __forceinline__ bool find_chunk(int b, int NT, int& t, int& rowstart, int& cnt) {
    int cb = 0;
#pragma unroll
    for (int tt = 0; tt < TT; tt++) {
        int lo = g_base[tt], hi = g_base[tt + 1];
        int ch = (hi - lo + NT - 1) / NT;
        if (b >= cb && b < cb + ch) {
            t = tt;
            rowstart = lo + (b - cb) * NT;
            cnt = min(NT, hi - rowstart);
            return true;
        }
        cb += ch;
    }
    return false;
}

// ---------------- partition pipeline ----------------
__global__ void k_zero() {
    int i = blockIdx.x * 256 + threadIdx.x;
    if (i < GRID_F) g_flag[i] = 0;
    if (i < TT) g_cnt[i] = 0;
}
__global__ void k_hist(const int* __restrict__ type_id) {
    __shared__ int sc[TT];
    if (threadIdx.x < TT) sc[threadIdx.x] = 0;
    __syncthreads();
    int i = blockIdx.x * 256 + threadIdx.x;
    int4 v = ((const int4*)type_id)[i];
    atomicAdd(&sc[v.x], 1);
    atomicAdd(&sc[v.y], 1);
    atomicAdd(&sc[v.z], 1);
    atomicAdd(&sc[v.w], 1);
    __syncthreads();
    if (threadIdx.x < TT) atomicAdd(&g_cnt[threadIdx.x], sc[threadIdx.x]);
}
__global__ void k_scan() {
    int b = 0;
#pragma unroll
    for (int t = 0; t < TT; t++) { g_base[t] = b; g_cursor[t] = b; b += g_cnt[t]; }
    g_base[TT] = b;
}
__global__ void k_scatter(const int* __restrict__ type_id) {
    __shared__ int w_off[8][TT];
    __shared__ int blk_base[TT];
    int n = blockIdx.x * 256 + threadIdx.x;
    int t = type_id[n];
    int w = threadIdx.x >> 5, lane = threadIdx.x & 31;
    int rank = 0;
#pragma unroll
    for (int tt = 0; tt < TT; tt++) {
        unsigned bm = __ballot_sync(0xffffffffu, t == tt);
        if (lane == 0) w_off[w][tt] = __popc(bm);
        if (t == tt) rank = __popc(bm & ((1u << lane) - 1));
    }
    __syncthreads();
    if (threadIdx.x < TT) {
        int tt = threadIdx.x, s = 0;
#pragma unroll
        for (int ww = 0; ww < 8; ww++) { int v = w_off[ww][tt]; w_off[ww][tt] = s; s += v; }
        blk_base[tt] = atomicAdd(&g_cursor[tt], s);
    }
    __syncthreads();
    g_sorted[blk_base[t] + w_off[w][t] + rank] = n;
}

// ---------------- forget role ----------------
__device__ __forceinline__ void forget_role(
    int fb, char* smem, uint32_t sb, int tid, int wid, int lane,
    const float* __restrict__ h, const float* __restrict__ c,
    const float* __restrict__ f_input, const float* __restrict__ U_f,
    const float* __restrict__ b_f, float* __restrict__ out)
{
    int t, rowstart, cnt;
    if (!find_chunk(fb, NTF, t, rowstart, cnt)) return;

    int* sh_node = (int*)(smem + F_NODE);
    float* sbf = (float*)(smem + F_BF);
    if (tid < NTF) sh_node[tid] = g_sorted[rowstart + min(tid, cnt - 1)];
    if (tid >= 128) sbf[tid - 128] = b_f[t * HH + (tid - 128)];
    __syncthreads();

    const int node0 = wid * 2, node1 = node0 + 1;
    const int nd0 = sh_node[node0], nd1 = sh_node[node1];

    // L2 prefetch for this warp's epilogue streams.
    {
        const float* cA = c + (size_t)nd0 * KK * HH;
        const float* cB = c + (size_t)nd1 * KK * HH;
        pf_l2(cA + lane * 32);
        pf_l2(cB + lane * 32);
        if (lane < 4) {
            pf_l2(f_input + (size_t)nd0 * HH + lane * 32);
            pf_l2(f_input + (size_t)nd1 * HH + lane * 32);
        }
    }

    // A loader + f32 hsum.
#pragma unroll
    for (int i = 0; i < 2; i++) {
        int task = tid + 256 * i;
        int j4 = task & 31, n = task >> 5;
        int nd = sh_node[n];
        float4 s = make_float4(0.f, 0.f, 0.f, 0.f);
#pragma unroll
        for (int ch = 0; ch < KK; ch++) {
            float4 v = *(const float4*)&h[((size_t)nd * KK + ch) * HH + j4 * 4];
            s.x += v.x; s.y += v.y; s.z += v.z; s.w += v.w;
            *(uint2*)(smem + F_A + (n * KK + ch) * ROWB + j4 * 8) =
                make_uint2(h2u(v.x, v.y), h2u(v.z, v.w));
        }
        *(float4*)&g_hsum[(size_t)nd * HH + j4 * 4] = s;
    }
    // B loader: B[k][n] from U_f[t][k][n].
#pragma unroll
    for (int i = 0; i < 16; i++) {
        int task = tid + 256 * i;
        int n4 = task & 31, k = task >> 5;
        float4 v = *(const float4*)&U_f[(size_t)t * HH * HH + (size_t)k * HH + n4 * 4];
        *(uint2*)(smem + F_B + k * ROWB + n4 * 8) = make_uint2(h2u(v.x, v.y), h2u(v.z, v.w));
    }
    __threadfence();   // publish hsum gpu-wide before the flag release below
    __syncthreads();
    if (tid == 0) st_rel(&g_flag[fb], 1);

    // Preload all A fragments.
    const int m0 = wid * 16;
    const uint32_t aaddr = sb + F_A + (m0 + (lane & 15)) * ROWB + ((lane >> 4) << 4);
    uint32_t af[8][4];
#pragma unroll
    for (int ks = 0; ks < 8; ks++) ldsm4(af[ks], aaddr + ks * 32);

    const int klocal = (lane & 7) + ((lane >> 3) & 1) * 8;
    const uint32_t btaddr = sb + F_B + klocal * ROWB + (lane >> 4) * 16;

    const int child = lane >> 2, q = lane & 3;
    const float* c0p = c + ((size_t)nd0 * KK + child) * HH;
    const float* c1p = c + ((size_t)nd1 * KK + child) * HH;
    const float* f0p = f_input + (size_t)nd0 * HH;
    const float* f1p = f_input + (size_t)nd1 * HH;

#pragma unroll 1
    for (int nb = 0; nb < 8; nb++) {
        const int colbase = nb * 16 + 2 * q;
        float2 cv00 = *(const float2*)(c0p + colbase);
        float2 cv01 = *(const float2*)(c0p + colbase + 8);
        float2 cv10 = *(const float2*)(c1p + colbase);
        float2 cv11 = *(const float2*)(c1p + colbase + 8);
        float2 f00 = *(const float2*)(f0p + colbase);
        float2 f01 = *(const float2*)(f0p + colbase + 8);
        float2 f10 = *(const float2*)(f1p + colbase);
        float2 f11 = *(const float2*)(f1p + colbase + 8);

        float acc0[4] = {0.f, 0.f, 0.f, 0.f};
        float acc1[4] = {0.f, 0.f, 0.f, 0.f};
#pragma unroll
        for (int ks = 0; ks < 8; ks++) {
            uint32_t bf4[4];
            ldsm4t(bf4, btaddr + ks * 16 * ROWB + nb * 32);
            mma16(acc0, af[ks], bf4[0], bf4[1]);
            mma16(acc1, af[ks], bf4[2], bf4[3]);
        }

        float2 bf0 = *(float2*)&sbf[colbase];
        float2 bf1 = *(float2*)&sbf[colbase + 8];

        float v00 = sigm(acc0[0] + f00.x + bf0.x) * cv00.x;
        float v01 = sigm(acc0[1] + f00.y + bf0.y) * cv00.y;
        float v10 = sigm(acc0[2] + f10.x + bf0.x) * cv10.x;
        float v11 = sigm(acc0[3] + f10.y + bf0.y) * cv10.y;
        float w00 = sigm(acc1[0] + f01.x + bf1.x) * cv01.x;
        float w01 = sigm(acc1[1] + f01.y + bf1.y) * cv01.y;
        float w10 = sigm(acc1[2] + f11.x + bf1.x) * cv11.x;
        float w11 = sigm(acc1[3] + f11.y + bf1.y) * cv11.y;
#pragma unroll
        for (int d = 4; d < 32; d <<= 1) {
            v00 += __shfl_xor_sync(0xffffffffu, v00, d);
            v01 += __shfl_xor_sync(0xffffffffu, v01, d);
            v10 += __shfl_xor_sync(0xffffffffu, v10, d);
            v11 += __shfl_xor_sync(0xffffffffu, v11, d);
            w00 += __shfl_xor_sync(0xffffffffu, w00, d);
            w01 += __shfl_xor_sync(0xffffffffu, w01, d);
            w10 += __shfl_xor_sync(0xffffffffu, w10, d);
            w11 += __shfl_xor_sync(0xffffffffu, w11, d);
        }
        const int node0v = node0 < cnt, node1v = node1 < cnt;
        if (lane < 4 && node0v) {
            *(float2*)&out[(size_t)nd0 * 512 + 384 + nb * 16 + 2 * lane] = make_float2(v00, v01);
            *(float2*)&out[(size_t)nd0 * 512 + 384 + nb * 16 + 8 + 2 * lane] = make_float2(w00, w01);
        }
        if (lane >= 4 && lane < 8 && node1v) {
            *(float2*)&out[(size_t)nd1 * 512 + 384 + nb * 16 + 2 * (lane - 4)] = make_float2(v10, v11);
            *(float2*)&out[(size_t)nd1 * 512 + 384 + nb * 16 + 8 + 2 * (lane - 4)] = make_float2(w10, w11);
        }
    }
}

// ---------------- iou role ----------------
__device__ __forceinline__ void iou_role(
    int ib, char* smem, uint32_t sb, int tid, int wid, int lane,
    const float* __restrict__ U_iou, const float* __restrict__ b_iou,
    float* __restrict__ out)
{
    int t, rowstart, cnt;
    if (!find_chunk(ib, NTI, t, rowstart, cnt)) return;

    // Which forget chunks produce our hsum rows? (same global enumeration as forget_role)
    {
        int cbF = 0;
#pragma unroll
        for (int tt = 0; tt < TT; tt++) {
            if (tt == t) break;
            cbF += (g_base[tt + 1] - g_base[tt] + NTF - 1) / NTF;
        }
        int lo = g_base[t];
        int bstart = cbF + (rowstart - lo) / NTF;
        int bend = cbF + (rowstart + cnt - 1 - lo) / NTF;
        if (tid <= bend - bstart) {
            const int* fp = &g_flag[bstart + tid];
            while (ld_acq(fp) == 0) { __nanosleep(64); }
        }
    }
    __syncthreads();

    int* sh_node = (int*)(smem + I_NODE);
    float* bst = (float*)(smem + I_BST);
    if (tid < 64) sh_node[tid] = g_sorted[rowstart + min(tid, cnt - 1)];
    if (tid < 128) {
        bst[tid] = b_iou[t * 384 + tid];
        bst[128 + tid] = b_iou[t * 384 + 128 + tid];
        bst[256 + tid] = b_iou[t * 384 + 256 + tid];
    }
    __syncthreads();

    // A loader: [64 m][128 k] fp16 from g_hsum (L2-fresh via ldcg).
#pragma unroll
    for (int i = 0; i < 8; i++) {
        int task = tid + 256 * i;
        int m = task >> 5, j4 = task & 31;
        float4 v = __ldcg((const float4*)&g_hsum[(size_t)sh_node[m] * HH + j4 * 4]);
        *(uint2*)(smem + I_A + m * ROWB + j4 * 8) = make_uint2(h2u(v.x, v.y), h2u(v.z, v.w));
    }
    __syncthreads();

    const int m0 = (wid >> 1) * 16;
    const int nh = wid & 1;
    const uint32_t aaddr = sb + I_A + (m0 + (lane & 15)) * ROWB + ((lane >> 4) << 4);
    uint32_t af[8][4];
#pragma unroll
    for (int ks = 0; ks < 8; ks++) ldsm4(af[ks], aaddr + ks * 32);

    const int klocal = (lane & 7) + ((lane >> 3) & 1) * 8;
    const uint32_t btaddr = sb + I_B + klocal * ROWB + (lane >> 4) * 16 + nh * 128;
    const int r0 = m0 + (lane >> 2), r1 = r0 + 8;
    const int q = lane & 3;
    const int nr0 = sh_node[r0], nr1 = sh_node[r1];

    for (int nc = 0; nc < 3; nc++) {
        if (nc > 0) __syncthreads();
#pragma unroll
        for (int i = 0; i < 16; i++) {
            int task = tid + 256 * i;
            int n4 = task & 31, k = task >> 5;
            float4 v = *(const float4*)&U_iou[(size_t)t * HH * 384 + (size_t)k * 384 + nc * 128 + n4 * 4];
            *(uint2*)(smem + I_B + k * ROWB + n4 * 8) = make_uint2(h2u(v.x, v.y), h2u(v.z, v.w));
        }
        __syncthreads();

#pragma unroll 1
        for (int nb = 0; nb < 4; nb++) {
            float acc0[4] = {0.f, 0.f, 0.f, 0.f};
            float acc1[4] = {0.f, 0.f, 0.f, 0.f};
#pragma unroll
            for (int ks = 0; ks < 8; ks++) {
                uint32_t bf4[4];
                ldsm4t(bf4, btaddr + ks * 16 * ROWB + nb * 32);
                mma16(acc0, af[ks], bf4[0], bf4[1]);
                mma16(acc1, af[ks], bf4[2], bf4[3]);
            }
            const int colbase = nh * 64 + nb * 16 + 2 * q;
            float2 b20 = *(float2*)&bst[nc * 128 + colbase];
            float2 b21 = *(float2*)&bst[nc * 128 + colbase + 8];
            if (r0 < cnt) {
                *(float2*)&out[(size_t)nr0 * 512 + nc * 128 + colbase] =
                    make_float2(acc0[0] + b20.x, acc0[1] + b20.y);
                *(float2*)&out[(size_t)nr0 * 512 + nc * 128 + colbase + 8] =
                    make_float2(acc1[0] + b21.x, acc1[1] + b21.y);
            }
            if (r1 < cnt) {
                *(float2*)&out[(size_t)nr1 * 512 + nc * 128 + colbase] =
                    make_float2(acc0[2] + b20.x, acc0[3] + b20.y);
                *(float2*)&out[(size_t)nr1 * 512 + nc * 128 + colbase + 8] =
                    make_float2(acc1[2] + b21.x, acc1[3] + b21.y);
            }
        }
    }
}

// ---------------- merged kernel ----------------
__global__ __launch_bounds__(256, 3) void k_main(
    const float* __restrict__ h, const float* __restrict__ c,
    const float* __restrict__ f_input,
    const float* __restrict__ U_iou, const float* __restrict__ b_iou,
    const float* __restrict__ U_f, const float* __restrict__ b_f,
    float* __restrict__ out)
{
    extern __shared__ __align__(1024) char smem[];
    const uint32_t sb = smem_u32(smem);
    const int tid = threadIdx.x, wid = tid >> 5, lane = tid & 31;
    if (blockIdx.x < GRID_F)
        forget_role(blockIdx.x, smem, sb, tid, wid, lane, h, c, f_input, U_f, b_f, out);
    else
        iou_role(blockIdx.x - GRID_F, smem, sb, tid, wid, lane, U_iou, b_iou, out);
}

// ---------------- launch ----------------
extern "C" void kernel_launch(void* const* d_in, const int* in_sizes, int n_in,
                              void* d_out, int out_size) {
    const float* h       = (const float*)d_in[0];
    const float* c       = (const float*)d_in[1];
    const float* f_input = (const float*)d_in[2];
    const int*   type_id = (const int*)d_in[3];
    const float* U_iou   = (const float*)d_in[4];
    const float* b_iou   = (const float*)d_in[5];
    const float* U_f     = (const float*)d_in[6];
    const float* b_f     = (const float*)d_in[7];
    float* out = (float*)d_out;

    static int attr_done = 0;
    if (!attr_done) {
        cudaFuncSetAttribute(k_main, cudaFuncAttributeMaxDynamicSharedMemorySize, F_SMEM);
        attr_done = 1;
    }

    k_zero<<<(GRID_F + 255) / 256, 256>>>();
    k_hist<<<NN / 1024, 256>>>(type_id);
    k_scan<<<1, 1>>>();
    k_scatter<<<NN / 256, 256>>>(type_id);
    k_main<<<GRID_F + GRID_I, 256, F_SMEM>>>(h, c, f_input, U_iou, b_iou, U_f, b_f, out);
}